// round 2
// baseline (speedup 1.0000x reference)
#include <cuda_runtime.h>
#include <cuda_bf16.h>
#include <math.h>

// Problem constants
#define BB 4
#define SS 2048
#define HH 512
#define II 1024
#define EE 8
#define KK 2
#define TT (BB*SS)          // 8192 tokens
#define TP (TT*KK)          // 16384 token-expert pairs

#define BM 64
#define BN 64
#define BK 16
#define ASTR 68             // padded A-tile stride (bank-conflict-free transposed stores)
#define MAX_TILES 264       // sum ceil(n_e/64) <= 256 + (E-1) = 263

// ---------------- device-global scratch (no cudaMalloc allowed) ----------------
__device__ float g_hinter[(size_t)TP * II];   // 64 MB intermediate (permuted row order)
__device__ int   g_perm[TP];                  // permuted pair index per routed position
__device__ int   g_off[EE + 1];               // expert segment offsets
__device__ int   g_tile_e[MAX_TILES];
__device__ int   g_tile_r[MAX_TILES];
__device__ int   g_ntiles;

// ---------------- routing: histogram + offsets + scatter + tile list ----------------
__global__ void route_kernel(const int* __restrict__ eidx) {
    __shared__ int s_cnt[EE];
    __shared__ int s_cur[EE];
    __shared__ int s_off[EE];
    int tid = threadIdx.x;
    if (tid < EE) { s_cnt[tid] = 0; s_cur[tid] = 0; }
    __syncthreads();
    for (int i = tid; i < TP; i += blockDim.x)
        atomicAdd(&s_cnt[eidx[i]], 1);
    __syncthreads();
    if (tid == 0) {
        int acc = 0, nt = 0;
        for (int e = 0; e < EE; e++) {
            s_off[e] = acc;
            g_off[e] = acc;
            for (int r = 0; r < s_cnt[e]; r += BM) {
                g_tile_e[nt] = e;
                g_tile_r[nt] = r;
                nt++;
            }
            acc += s_cnt[e];
        }
        g_off[EE] = acc;
        g_ntiles = nt;
    }
    __syncthreads();
    for (int i = tid; i < TP; i += blockDim.x) {
        int e = eidx[i];
        int pos = atomicAdd(&s_cur[e], 1);
        g_perm[s_off[e] + pos] = i;
    }
}

__device__ __forceinline__ float silu(float g) {
    return g / (1.0f + expf(-g));
}

// ---------------- GEMM1: X_gathered @ w13[e], fused SwiGLU -> g_hinter ----------------
// grid: (MAX_TILES, II/BN). Block computes BM rows x BN gate cols + BN up cols.
__global__ __launch_bounds__(256) void gemm1_kernel(const float* __restrict__ x,
                                                    const float* __restrict__ w13) {
    int bx = blockIdx.x;
    if (bx >= g_ntiles) return;
    const int e   = g_tile_e[bx];
    const int r0  = g_tile_r[bx];
    const int off = g_off[e];
    const int ne  = g_off[e + 1] - off;
    const int rows = min(BM, ne - r0);
    const int n0  = blockIdx.y * BN;

    __shared__ __align__(16) float As[BK * ASTR];
    __shared__ __align__(16) float Bg[BK * BN];
    __shared__ __align__(16) float Bu[BK * BN];
    __shared__ int s_tok[BM];

    const int tid = threadIdx.x;
    if (tid < BM)
        s_tok[tid] = (tid < rows) ? (g_perm[off + r0 + tid] / KK) : -1;
    __syncthreads();

    const float* wb = w13 + (size_t)e * HH * (2 * II);

    // loader mapping
    const int am = tid >> 2;            // 0..63 (A row)
    const int ak = (tid & 3) * 4;       // 0,4,8,12 (A k within tile)
    const int bk = tid >> 4;            // 0..15 (B k within tile)
    const int bn = (tid & 15) * 4;      // 0..60 (B col within tile)
    const int tokm = s_tok[am];

    const int tx = tid & 15, ty = tid >> 4;

    float accg[16], accu[16];
#pragma unroll
    for (int i = 0; i < 16; i++) { accg[i] = 0.0f; accu[i] = 0.0f; }

    for (int k0 = 0; k0 < HH; k0 += BK) {
        float4 av = make_float4(0.f, 0.f, 0.f, 0.f);
        if (tokm >= 0)
            av = *reinterpret_cast<const float4*>(x + (size_t)tokm * HH + k0 + ak);
        const size_t brow = (size_t)(k0 + bk) * (2 * II);
        float4 bgv = *reinterpret_cast<const float4*>(wb + brow + n0 + bn);
        float4 buv = *reinterpret_cast<const float4*>(wb + brow + II + n0 + bn);
        __syncthreads();
        As[(ak + 0) * ASTR + am] = av.x;
        As[(ak + 1) * ASTR + am] = av.y;
        As[(ak + 2) * ASTR + am] = av.z;
        As[(ak + 3) * ASTR + am] = av.w;
        *reinterpret_cast<float4*>(&Bg[bk * BN + bn]) = bgv;
        *reinterpret_cast<float4*>(&Bu[bk * BN + bn]) = buv;
        __syncthreads();
#pragma unroll
        for (int kk = 0; kk < BK; kk++) {
            const float4 a  = *reinterpret_cast<const float4*>(&As[kk * ASTR + 4 * ty]);
            const float4 bg = *reinterpret_cast<const float4*>(&Bg[kk * BN + 4 * tx]);
            const float4 bu = *reinterpret_cast<const float4*>(&Bu[kk * BN + 4 * tx]);
            const float ar[4]  = {a.x, a.y, a.z, a.w};
            const float bgr[4] = {bg.x, bg.y, bg.z, bg.w};
            const float bur[4] = {bu.x, bu.y, bu.z, bu.w};
#pragma unroll
            for (int i2 = 0; i2 < 4; i2++) {
#pragma unroll
                for (int j = 0; j < 4; j++) {
                    accg[i2 * 4 + j] = fmaf(ar[i2], bgr[j], accg[i2 * 4 + j]);
                    accu[i2 * 4 + j] = fmaf(ar[i2], bur[j], accu[i2 * 4 + j]);
                }
            }
        }
    }

#pragma unroll
    for (int i2 = 0; i2 < 4; i2++) {
        const int m = 4 * ty + i2;
        if (m < rows) {
            const size_t prow = (size_t)(off + r0 + m);
            float4 hv;
            hv.x = silu(accg[i2 * 4 + 0]) * accu[i2 * 4 + 0];
            hv.y = silu(accg[i2 * 4 + 1]) * accu[i2 * 4 + 1];
            hv.z = silu(accg[i2 * 4 + 2]) * accu[i2 * 4 + 2];
            hv.w = silu(accg[i2 * 4 + 3]) * accu[i2 * 4 + 3];
            *reinterpret_cast<float4*>(g_hinter + prow * II + n0 + 4 * tx) = hv;
        }
    }
}

// ---------------- GEMM2: h_inter @ w2[e] -> scattered output rows ----------------
// grid: (MAX_TILES, HH/BN).
__global__ __launch_bounds__(256) void gemm2_kernel(const float* __restrict__ w2,
                                                    float* __restrict__ out) {
    int bx = blockIdx.x;
    if (bx >= g_ntiles) return;
    const int e   = g_tile_e[bx];
    const int r0  = g_tile_r[bx];
    const int off = g_off[e];
    const int ne  = g_off[e + 1] - off;
    const int rows = min(BM, ne - r0);
    const int n0  = blockIdx.y * BN;

    __shared__ __align__(16) float As[BK * ASTR];
    __shared__ __align__(16) float Bs[BK * BN];

    const int tid = threadIdx.x;
    const int am = tid >> 2;
    const int ak = (tid & 3) * 4;
    const int bk = tid >> 4;
    const int bn = (tid & 15) * 4;
    const int tx = tid & 15, ty = tid >> 4;

    const float* wb = w2 + (size_t)e * II * HH;
    const bool avalid = (am < rows);
    const float* arow = g_hinter + (size_t)(off + r0 + am) * II;

    float acc[16];
#pragma unroll
    for (int i = 0; i < 16; i++) acc[i] = 0.0f;

    for (int k0 = 0; k0 < II; k0 += BK) {
        float4 av = make_float4(0.f, 0.f, 0.f, 0.f);
        if (avalid)
            av = *reinterpret_cast<const float4*>(arow + k0 + ak);
        float4 bv = *reinterpret_cast<const float4*>(wb + (size_t)(k0 + bk) * HH + n0 + bn);
        __syncthreads();
        As[(ak + 0) * ASTR + am] = av.x;
        As[(ak + 1) * ASTR + am] = av.y;
        As[(ak + 2) * ASTR + am] = av.z;
        As[(ak + 3) * ASTR + am] = av.w;
        *reinterpret_cast<float4*>(&Bs[bk * BN + bn]) = bv;
        __syncthreads();
#pragma unroll
        for (int kk = 0; kk < BK; kk++) {
            const float4 a = *reinterpret_cast<const float4*>(&As[kk * ASTR + 4 * ty]);
            const float4 b = *reinterpret_cast<const float4*>(&Bs[kk * BN + 4 * tx]);
            const float ar[4] = {a.x, a.y, a.z, a.w};
            const float br[4] = {b.x, b.y, b.z, b.w};
#pragma unroll
            for (int i2 = 0; i2 < 4; i2++) {
#pragma unroll
                for (int j = 0; j < 4; j++)
                    acc[i2 * 4 + j] = fmaf(ar[i2], br[j], acc[i2 * 4 + j]);
            }
        }
    }

#pragma unroll
    for (int i2 = 0; i2 < 4; i2++) {
        const int m = 4 * ty + i2;
        if (m < rows) {
            const int pair = g_perm[off + r0 + m];
            float4 ov;
            ov.x = acc[i2 * 4 + 0];
            ov.y = acc[i2 * 4 + 1];
            ov.z = acc[i2 * 4 + 2];
            ov.w = acc[i2 * 4 + 3];
            *reinterpret_cast<float4*>(out + (size_t)pair * HH + n0 + 4 * tx) = ov;
        }
    }
}

// ---------------- launch ----------------
extern "C" void kernel_launch(void* const* d_in, const int* in_sizes, int n_in,
                              void* d_out, int out_size) {
    const float* x    = (const float*)d_in[0];   // (B,S,H) fp32
    const int*   eidx = (const int*)d_in[1];     // (B,S,K) int32
    const float* w13  = (const float*)d_in[2];   // (E,H,2I) fp32
    const float* w2   = (const float*)d_in[3];   // (E,I,H) fp32
    float* out = (float*)d_out;                  // (B,S,K,H) fp32

    route_kernel<<<1, 256>>>(eidx);
    gemm1_kernel<<<dim3(MAX_TILES, II / BN), 256>>>(x, w13);
    gemm2_kernel<<<dim3(MAX_TILES, HH / BN), 256>>>(w2, out);
}

// round 3
// speedup vs baseline: 1.6112x; 1.6112x over previous
#include <cuda_runtime.h>
#include <cuda_bf16.h>
#include <math.h>
#include <stdint.h>

// Problem constants
#define BB 4
#define SS 2048
#define HH 512
#define II 1024
#define EE 8
#define KK 2
#define TT (BB*SS)          // 8192 tokens
#define TP (TT*KK)          // 16384 token-expert pairs

// ---------------- device-global scratch ----------------
__device__ float g_hinter[(size_t)TP * II];   // 64 MB intermediate (permuted rows)
__device__ int   g_perm[TP];
__device__ int   g_off[EE + 1];

// ---------------- routing ----------------
__global__ void route_kernel(const int* __restrict__ eidx) {
    __shared__ int s_cnt[EE];
    __shared__ int s_cur[EE];
    __shared__ int s_off[EE];
    int tid = threadIdx.x;
    if (tid < EE) { s_cnt[tid] = 0; s_cur[tid] = 0; }
    __syncthreads();
    for (int i = tid; i < TP; i += blockDim.x)
        atomicAdd(&s_cnt[eidx[i]], 1);
    __syncthreads();
    if (tid == 0) {
        int acc = 0;
        for (int e = 0; e < EE; e++) { s_off[e] = acc; g_off[e] = acc; acc += s_cnt[e]; }
        g_off[EE] = acc;
    }
    __syncthreads();
    for (int i = tid; i < TP; i += blockDim.x) {
        int e = eidx[i];
        int pos = atomicAdd(&s_cur[e], 1);
        g_perm[s_off[e] + pos] = i;
    }
}

// ---------------- helpers ----------------
__device__ __forceinline__ uint32_t f2tf32(float f) {
    uint32_t r;
    asm("cvt.rna.tf32.f32 %0, %1;" : "=r"(r) : "f"(f));
    return r;
}

__device__ __forceinline__ void mma_tf32(float* d, const uint32_t* a, uint32_t b0, uint32_t b1) {
    asm volatile(
        "mma.sync.aligned.m16n8k8.row.col.f32.tf32.tf32.f32 "
        "{%0,%1,%2,%3}, {%4,%5,%6,%7}, {%8,%9}, {%0,%1,%2,%3};\n"
        : "+f"(d[0]), "+f"(d[1]), "+f"(d[2]), "+f"(d[3])
        : "r"(a[0]), "r"(a[1]), "r"(a[2]), "r"(a[3]), "r"(b0), "r"(b1));
}

__device__ __forceinline__ float silu(float g) { return g / (1.0f + expf(-g)); }

// ======================= GEMM1 =======================
// Block: (expert e, n-range of 32 gate+32 up cols, m-chunk). B resident full K=512.
// BM=128 per M-iter. 8 warps: wm=wid&3 (rows wm*32..+31), mat=wid>>2 (0=gate,1=up).
// Warp computes 32x32 of its matrix via m16n8k8 (mt 0..1, nt 0..3).
#define BN1 32
#define BK 16
#define NK1 (HH/BK)        // 32
#define BSTR1 516          // K + 4
#define ASTR1 20           // BK + 4
#define NC1 2

#define SM1_BG 0
#define SM1_BU (32*BSTR1*4)                 // 66048
#define SM1_EPI (2*32*BSTR1*4)              // 132096
#define SM1_A0  SM1_EPI
#define SM1_A1  (SM1_EPI + 128*ASTR1*4)     // +10240
#define SM1_TOK (SM1_EPI + 2*128*36*4)      // 132096+36864 = 168960
#define SM1_TOTAL (SM1_TOK + 512)           // 169472

__global__ __launch_bounds__(256) void gemm1_kernel(const float* __restrict__ x,
                                                    const float* __restrict__ w13) {
    extern __shared__ __align__(16) char smem[];
    uint32_t* sBg = (uint32_t*)(smem + SM1_BG);
    uint32_t* sBu = (uint32_t*)(smem + SM1_BU);
    int* s_tok = (int*)(smem + SM1_TOK);

    const int bx = blockIdx.x;
    const int e = bx >> 6;
    const int nIdx = (bx >> 1) & 31;
    const int c = bx & 1;
    const int n0 = nIdx * BN1;

    const int off = g_off[e];
    const int ne = g_off[e + 1] - off;

    const int tid = threadIdx.x;
    const int wid = tid >> 5;
    const int lane = tid & 31;
    const int g = lane >> 2;
    const int t4 = lane & 3;
    const int wm = wid & 3;
    const int mat = wid >> 2;
    const int wrow = wm * 32;

    const float* wb = w13 + (size_t)e * HH * (2 * II);

    // ---- stage B (gate + up), convert to tf32, layout [n][K] stride BSTR1 ----
    for (int idx = tid; idx < HH * 8; idx += 256) {
        int k = idx >> 3;
        int f = idx & 7;
        float4 bg = *(const float4*)(wb + (size_t)k * (2 * II) + n0 + f * 4);
        float4 bu = *(const float4*)(wb + (size_t)k * (2 * II) + II + n0 + f * 4);
        sBg[(f * 4 + 0) * BSTR1 + k] = f2tf32(bg.x);
        sBg[(f * 4 + 1) * BSTR1 + k] = f2tf32(bg.y);
        sBg[(f * 4 + 2) * BSTR1 + k] = f2tf32(bg.z);
        sBg[(f * 4 + 3) * BSTR1 + k] = f2tf32(bg.w);
        sBu[(f * 4 + 0) * BSTR1 + k] = f2tf32(bu.x);
        sBu[(f * 4 + 1) * BSTR1 + k] = f2tf32(bu.y);
        sBu[(f * 4 + 2) * BSTR1 + k] = f2tf32(bu.z);
        sBu[(f * 4 + 3) * BSTR1 + k] = f2tf32(bu.w);
    }
    const uint32_t* sB = mat ? sBu : sBg;

    const int rr = tid >> 1;           // A staging row 0..127
    const int kq = (tid & 1) * 8;      // A staging k offset 0/8

    for (int m0 = c * 128; m0 < ne; m0 += NC1 * 128) {
        const int rows = min(128, ne - m0);

        __syncthreads();   // B staged (first iter) / epilogue buffers free (later iters)
        if (tid < 128) {
            int m = m0 + tid;
            s_tok[tid] = (m < ne) ? (g_perm[off + m] >> 1) : -1;
        }
        __syncthreads();

        const int tok = s_tok[rr];
        const float* xrow = (tok >= 0) ? (x + (size_t)tok * HH) : nullptr;

        float acc[2][4][4];
#pragma unroll
        for (int i = 0; i < 2; i++)
#pragma unroll
            for (int j = 0; j < 4; j++)
#pragma unroll
                for (int q = 0; q < 4; q++) acc[i][j][q] = 0.0f;

        float4 pa, pb;
        if (xrow) { pa = *(const float4*)(xrow + kq); pb = *(const float4*)(xrow + kq + 4); }
        else { pa = make_float4(0.f,0.f,0.f,0.f); pb = pa; }
        {
            uint32_t* As = (uint32_t*)(smem + SM1_A0);
            As[rr * ASTR1 + kq + 0] = f2tf32(pa.x);
            As[rr * ASTR1 + kq + 1] = f2tf32(pa.y);
            As[rr * ASTR1 + kq + 2] = f2tf32(pa.z);
            As[rr * ASTR1 + kq + 3] = f2tf32(pa.w);
            As[rr * ASTR1 + kq + 4] = f2tf32(pb.x);
            As[rr * ASTR1 + kq + 5] = f2tf32(pb.y);
            As[rr * ASTR1 + kq + 6] = f2tf32(pb.z);
            As[rr * ASTR1 + kq + 7] = f2tf32(pb.w);
        }
        __syncthreads();

        for (int ks = 0; ks < NK1; ks++) {
            // prefetch next A k-slab
            if (ks + 1 < NK1 && xrow) {
                pa = *(const float4*)(xrow + (ks + 1) * BK + kq);
                pb = *(const float4*)(xrow + (ks + 1) * BK + kq + 4);
            }
            const uint32_t* As = (uint32_t*)(smem + ((ks & 1) ? SM1_A1 : SM1_A0));
            const int k0 = ks * BK;
#pragma unroll
            for (int kh = 0; kh < 2; kh++) {
                uint32_t a[2][4];
#pragma unroll
                for (int mt = 0; mt < 2; mt++) {
                    int r = wrow + mt * 16 + g;
                    a[mt][0] = As[r * ASTR1 + kh * 8 + t4];
                    a[mt][1] = As[(r + 8) * ASTR1 + kh * 8 + t4];
                    a[mt][2] = As[r * ASTR1 + kh * 8 + t4 + 4];
                    a[mt][3] = As[(r + 8) * ASTR1 + kh * 8 + t4 + 4];
                }
#pragma unroll
                for (int nt = 0; nt < 4; nt++) {
                    uint32_t b0 = sB[(nt * 8 + g) * BSTR1 + k0 + kh * 8 + t4];
                    uint32_t b1 = sB[(nt * 8 + g) * BSTR1 + k0 + kh * 8 + t4 + 4];
                    mma_tf32(acc[0][nt], a[0], b0, b1);
                    mma_tf32(acc[1][nt], a[1], b0, b1);
                }
            }
            if (ks + 1 < NK1) {
                uint32_t* Asn = (uint32_t*)(smem + (((ks + 1) & 1) ? SM1_A1 : SM1_A0));
                Asn[rr * ASTR1 + kq + 0] = f2tf32(pa.x);
                Asn[rr * ASTR1 + kq + 1] = f2tf32(pa.y);
                Asn[rr * ASTR1 + kq + 2] = f2tf32(pa.z);
                Asn[rr * ASTR1 + kq + 3] = f2tf32(pa.w);
                Asn[rr * ASTR1 + kq + 4] = f2tf32(pb.x);
                Asn[rr * ASTR1 + kq + 5] = f2tf32(pb.y);
                Asn[rr * ASTR1 + kq + 6] = f2tf32(pb.z);
                Asn[rr * ASTR1 + kq + 7] = f2tf32(pb.w);
            }
            __syncthreads();
        }

        // ---- epilogue: exchange gate/up via smem, fuse SwiGLU, store ----
        float* sE = (float*)(smem + SM1_EPI) + (size_t)mat * 128 * 36;
#pragma unroll
        for (int mt = 0; mt < 2; mt++) {
#pragma unroll
            for (int nt = 0; nt < 4; nt++) {
                int r = wrow + mt * 16 + g;
                int col = nt * 8 + 2 * t4;
                sE[r * 36 + col]       = acc[mt][nt][0];
                sE[r * 36 + col + 1]   = acc[mt][nt][1];
                sE[(r + 8) * 36 + col]     = acc[mt][nt][2];
                sE[(r + 8) * 36 + col + 1] = acc[mt][nt][3];
            }
        }
        __syncthreads();
        const float* sG = (const float*)(smem + SM1_EPI);
        const float* sU = sG + 128 * 36;
#pragma unroll
        for (int j = 0; j < 4; j++) {
            int idx = tid + 256 * j;
            int row = idx >> 3;
            int f = idx & 7;
            if (row < rows) {
                float4 gv = *(const float4*)(sG + row * 36 + f * 4);
                float4 uv = *(const float4*)(sU + row * 36 + f * 4);
                float4 hv;
                hv.x = silu(gv.x) * uv.x;
                hv.y = silu(gv.y) * uv.y;
                hv.z = silu(gv.z) * uv.z;
                hv.w = silu(gv.w) * uv.w;
                *(float4*)(g_hinter + (size_t)(off + m0 + row) * II + n0 + f * 4) = hv;
            }
        }
    }
}

// ======================= GEMM2 =======================
// Block: (expert e, n-range 32 cols, m-chunk). B resident full K=1024.
// BM=256 per M-iter. 8 warps: wm=wid, warp rows wm*32, 32x32 tile.
#define BN2 32
#define NK2 (II/BK)        // 64
#define BSTR2 1028         // K + 4
#define NC2 4

#define SM2_B 0
#define SM2_A0 (32*BSTR2*4)               // 131584
#define SM2_A1 (SM2_A0 + 256*ASTR1*4)     // +20480
#define SM2_TOTAL (SM2_A1 + 256*ASTR1*4)  // 172544

__global__ __launch_bounds__(256) void gemm2_kernel(const float* __restrict__ w2,
                                                    float* __restrict__ out) {
    extern __shared__ __align__(16) char smem[];
    uint32_t* sB = (uint32_t*)(smem + SM2_B);

    const int bx = blockIdx.x;
    const int e = bx >> 6;
    const int nIdx = (bx >> 2) & 15;
    const int c = bx & 3;
    const int n0 = nIdx * BN2;

    const int off = g_off[e];
    const int ne = g_off[e + 1] - off;

    const int tid = threadIdx.x;
    const int wid = tid >> 5;
    const int lane = tid & 31;
    const int g = lane >> 2;
    const int t4 = lane & 3;
    const int wrow = wid * 32;

    const float* wb = w2 + (size_t)e * II * HH;

    // ---- stage B, tf32, layout [n][K] stride BSTR2 ----
    for (int idx = tid; idx < II * 8; idx += 256) {
        int k = idx >> 3;
        int f = idx & 7;
        float4 bv = *(const float4*)(wb + (size_t)k * HH + n0 + f * 4);
        sB[(f * 4 + 0) * BSTR2 + k] = f2tf32(bv.x);
        sB[(f * 4 + 1) * BSTR2 + k] = f2tf32(bv.y);
        sB[(f * 4 + 2) * BSTR2 + k] = f2tf32(bv.z);
        sB[(f * 4 + 3) * BSTR2 + k] = f2tf32(bv.w);
    }

    const int rr = tid >> 2;          // staging row base 0..63 (+64p)
    const int kq = (tid & 3) * 4;     // staging k offset

    for (int m0 = c * 256; m0 < ne; m0 += NC2 * 256) {
        const int rows = min(256, ne - m0);

        const float* hrow[4];
#pragma unroll
        for (int p = 0; p < 4; p++) {
            int m = m0 + rr + 64 * p;
            hrow[p] = (m < ne) ? (g_hinter + (size_t)(off + m) * II) : nullptr;
        }

        float acc[2][4][4];
#pragma unroll
        for (int i = 0; i < 2; i++)
#pragma unroll
            for (int j = 0; j < 4; j++)
#pragma unroll
                for (int q = 0; q < 4; q++) acc[i][j][q] = 0.0f;

        float4 pf[4];
#pragma unroll
        for (int p = 0; p < 4; p++)
            pf[p] = hrow[p] ? *(const float4*)(hrow[p] + kq) : make_float4(0.f,0.f,0.f,0.f);
        __syncthreads();  // prev iter epilogue done; (first iter: B staged)
        {
            uint32_t* As = (uint32_t*)(smem + SM2_A0);
#pragma unroll
            for (int p = 0; p < 4; p++) {
                As[(rr + 64 * p) * ASTR1 + kq + 0] = f2tf32(pf[p].x);
                As[(rr + 64 * p) * ASTR1 + kq + 1] = f2tf32(pf[p].y);
                As[(rr + 64 * p) * ASTR1 + kq + 2] = f2tf32(pf[p].z);
                As[(rr + 64 * p) * ASTR1 + kq + 3] = f2tf32(pf[p].w);
            }
        }
        __syncthreads();

        for (int ks = 0; ks < NK2; ks++) {
            if (ks + 1 < NK2) {
#pragma unroll
                for (int p = 0; p < 4; p++)
                    pf[p] = hrow[p] ? *(const float4*)(hrow[p] + (ks + 1) * BK + kq)
                                    : make_float4(0.f,0.f,0.f,0.f);
            }
            const uint32_t* As = (uint32_t*)(smem + ((ks & 1) ? SM2_A1 : SM2_A0));
            const int k0 = ks * BK;
#pragma unroll
            for (int kh = 0; kh < 2; kh++) {
                uint32_t a[2][4];
#pragma unroll
                for (int mt = 0; mt < 2; mt++) {
                    int r = wrow + mt * 16 + g;
                    a[mt][0] = As[r * ASTR1 + kh * 8 + t4];
                    a[mt][1] = As[(r + 8) * ASTR1 + kh * 8 + t4];
                    a[mt][2] = As[r * ASTR1 + kh * 8 + t4 + 4];
                    a[mt][3] = As[(r + 8) * ASTR1 + kh * 8 + t4 + 4];
                }
#pragma unroll
                for (int nt = 0; nt < 4; nt++) {
                    uint32_t b0 = sB[(nt * 8 + g) * BSTR2 + k0 + kh * 8 + t4];
                    uint32_t b1 = sB[(nt * 8 + g) * BSTR2 + k0 + kh * 8 + t4 + 4];
                    mma_tf32(acc[0][nt], a[0], b0, b1);
                    mma_tf32(acc[1][nt], a[1], b0, b1);
                }
            }
            if (ks + 1 < NK2) {
                uint32_t* Asn = (uint32_t*)(smem + (((ks + 1) & 1) ? SM2_A1 : SM2_A0));
#pragma unroll
                for (int p = 0; p < 4; p++) {
                    Asn[(rr + 64 * p) * ASTR1 + kq + 0] = f2tf32(pf[p].x);
                    Asn[(rr + 64 * p) * ASTR1 + kq + 1] = f2tf32(pf[p].y);
                    Asn[(rr + 64 * p) * ASTR1 + kq + 2] = f2tf32(pf[p].z);
                    Asn[(rr + 64 * p) * ASTR1 + kq + 3] = f2tf32(pf[p].w);
                }
            }
            __syncthreads();
        }

        // ---- epilogue: scatter via perm, direct STG.64 ----
#pragma unroll
        for (int mt = 0; mt < 2; mt++) {
            int r0l = wrow + mt * 16 + g;
            int r1l = r0l + 8;
            int pair0 = (r0l < rows) ? g_perm[off + m0 + r0l] : -1;
            int pair1 = (r1l < rows) ? g_perm[off + m0 + r1l] : -1;
#pragma unroll
            for (int nt = 0; nt < 4; nt++) {
                int col = n0 + nt * 8 + 2 * t4;
                if (pair0 >= 0) {
                    float2 v = make_float2(acc[mt][nt][0], acc[mt][nt][1]);
                    *(float2*)(out + (size_t)pair0 * HH + col) = v;
                }
                if (pair1 >= 0) {
                    float2 v = make_float2(acc[mt][nt][2], acc[mt][nt][3]);
                    *(float2*)(out + (size_t)pair1 * HH + col) = v;
                }
            }
        }
    }
}

// ---------------- launch ----------------
extern "C" void kernel_launch(void* const* d_in, const int* in_sizes, int n_in,
                              void* d_out, int out_size) {
    const float* x    = (const float*)d_in[0];
    const int*   eidx = (const int*)d_in[1];
    const float* w13  = (const float*)d_in[2];
    const float* w2   = (const float*)d_in[3];
    float* out = (float*)d_out;

    cudaFuncSetAttribute(gemm1_kernel, cudaFuncAttributeMaxDynamicSharedMemorySize, SM1_TOTAL);
    cudaFuncSetAttribute(gemm2_kernel, cudaFuncAttributeMaxDynamicSharedMemorySize, SM2_TOTAL);

    route_kernel<<<1, 1024>>>(eidx);
    gemm1_kernel<<<EE * 32 * NC1, 256, SM1_TOTAL>>>(x, w13);
    gemm2_kernel<<<EE * 16 * NC2, 256, SM2_TOTAL>>>(w2, out);
}

// round 13
// speedup vs baseline: 5.0789x; 3.1522x over previous
#include <cuda_runtime.h>
#include <math.h>
#include <stdint.h>

// Problem constants
#define HH 512
#define II 1024
#define EE 8
#define TT 8192
#define TP 16384

#define BM 128
#define BK 32
#define MAXT 136            // max 128-row m-tiles: 16384/128 + 7

// smem layout (bytes)
#define ASTR 36             // floats per A row (BK + 4)
#define BSTR 136            // floats per B k-row (BN + 8)
#define ABYTES (BM*ASTR*4)      // 18432
#define BBYTES (BK*BSTR*4)      // 17408
#define SM_TOK 0                // 128 ints
#define SM_A   512
#define SM_B   (SM_A + 2*ABYTES)            // 37376
#define SM_TOT (SM_B + 2*BBYTES)            // 72192

#define NS1 (HH/BK)         // 16
#define NS2 (II/BK)         // 32

// ---------------- device-global scratch ----------------
__device__ float g_hinter[(size_t)TP * II];   // 64MB (tf32-rounded by gemm1)
__device__ int   g_perm[TP];
__device__ int   g_off[EE + 1];
__device__ int   g_mt_e[MAXT];
__device__ int   g_mt_r[MAXT];
__device__ int   g_nmt;

// ---------------- helpers ----------------
__device__ __forceinline__ float rnaf(float f) {
    uint32_t r;
    asm("cvt.rna.tf32.f32 %0, %1;" : "=r"(r) : "f"(f));
    return __uint_as_float(r);
}
__device__ __forceinline__ void mma_tf32(float* d, const uint32_t* a, uint32_t b0, uint32_t b1) {
    asm volatile(
        "mma.sync.aligned.m16n8k8.row.col.f32.tf32.tf32.f32 "
        "{%0,%1,%2,%3}, {%4,%5,%6,%7}, {%8,%9}, {%0,%1,%2,%3};\n"
        : "+f"(d[0]), "+f"(d[1]), "+f"(d[2]), "+f"(d[3])
        : "r"(a[0]), "r"(a[1]), "r"(a[2]), "r"(a[3]), "r"(b0), "r"(b1));
}
__device__ __forceinline__ float silu(float g) { return g / (1.0f + expf(-g)); }

// ---------------- routing ----------------
__global__ void route_kernel(const int* __restrict__ eidx) {
    __shared__ int s_cnt[EE], s_cur[EE], s_off[EE];
    int tid = threadIdx.x;
    if (tid < EE) { s_cnt[tid] = 0; s_cur[tid] = 0; }
    __syncthreads();
    for (int i = tid; i < TP; i += blockDim.x) atomicAdd(&s_cnt[eidx[i]], 1);
    __syncthreads();
    if (tid == 0) {
        int acc = 0, nm = 0;
        for (int e = 0; e < EE; e++) {
            s_off[e] = acc; g_off[e] = acc;
            for (int r = 0; r < s_cnt[e]; r += BM) { g_mt_e[nm] = e; g_mt_r[nm] = r; nm++; }
            acc += s_cnt[e];
        }
        g_off[EE] = acc; g_nmt = nm;
    }
    __syncthreads();
    for (int i = tid; i < TP; i += blockDim.x) {
        int e = eidx[i];
        int p = atomicAdd(&s_cur[e], 1);
        g_perm[s_off[e] + p] = i;
    }
}

// ======================= GEMM1: x @ w13 (+fused SwiGLU) -> g_hinter =======================
// grid (MAXT, II/64). B tile: 64 gate + 64 up cols interleaved by 8.
__global__ __launch_bounds__(256, 2) void gemm1_kernel(const float* __restrict__ x,
                                                       const float* __restrict__ w13) {
    extern __shared__ __align__(16) char smem[];
    const int mtile = blockIdx.x;
    if (mtile >= g_nmt) return;
    const int chunk = blockIdx.y;
    const int e = g_mt_e[mtile], r0 = g_mt_r[mtile];
    const int off = g_off[e], ne = g_off[e + 1] - off;
    const int rows = min(BM, ne - r0);

    const int tid = threadIdx.x, wid = tid >> 5, lane = tid & 31;
    const int g = lane >> 2, t4 = lane & 3;
    const int mw = wid & 1, nw = wid >> 1;
    const int wrow = mw * 64, nb = nw * 32;

    int* stok = (int*)(smem + SM_TOK);
    if (tid < BM) {
        int m = r0 + tid;
        stok[tid] = (m < ne) ? (g_perm[off + m] >> 1) : 0;  // clamp; invalid rows discarded later
    }
    __syncthreads();

    const float* wb = w13 + (size_t)e * HH * (2 * II);
    const int n0p = chunk * 64;

    // per-thread staging geometry
    const int f = tid & 7;                  // A: float4 slot within row
    const int rowb = tid >> 3;              // A: row base (+32 per j)
    const int c4 = tid & 31;                // B: float4 col
    const int kkb = tid >> 5;               // B: k-row base (+8 per j)
    const int c0 = c4 * 4;
    const int w16 = c0 & 15, pg = c0 >> 4;
    const int bcol = (w16 < 8) ? (n0p + pg * 8 + w16) : (II + n0p + pg * 8 + (w16 - 8));

    const float* aSrc[4];
#pragma unroll
    for (int j = 0; j < 4; j++)
        aSrc[j] = x + (size_t)stok[rowb + 32 * j] * HH + f * 4;
    const float* bSrc = wb + (size_t)kkb * (2 * II) + bcol;
    const int aOff0 = rowb * ASTR + f * 4;      // +32*ASTR per j
    const int bOff0 = kkb * BSTR + c0;          // +8*BSTR per j

    float4 pa[4], pb[4];
    auto ldg = [&](int s) {
        const int k0 = s * BK;
#pragma unroll
        for (int j = 0; j < 4; j++) {
            pa[j] = *(const float4*)(aSrc[j] + k0);
            pb[j] = *(const float4*)(bSrc + (size_t)(k0 + 8 * j * 0) * 0 + (size_t)k0 * (2 * II) + (size_t)j * 8 * (2 * II));
        }
    };
    auto sts = [&](int s) {
        float* A = (float*)(smem + SM_A + (s & 1) * ABYTES);
        float* B = (float*)(smem + SM_B + (s & 1) * BBYTES);
#pragma unroll
        for (int j = 0; j < 4; j++) {
            float4 ra = make_float4(rnaf(pa[j].x), rnaf(pa[j].y), rnaf(pa[j].z), rnaf(pa[j].w));
            float4 rb = make_float4(rnaf(pb[j].x), rnaf(pb[j].y), rnaf(pb[j].z), rnaf(pb[j].w));
            *(float4*)(A + aOff0 + j * 32 * ASTR) = ra;
            *(float4*)(B + bOff0 + j * 8 * BSTR) = rb;
        }
    };

    float acc[4][4][4];
#pragma unroll
    for (int a = 0; a < 4; a++)
#pragma unroll
        for (int b = 0; b < 4; b++)
#pragma unroll
            for (int q = 0; q < 4; q++) acc[a][b][q] = 0.0f;

    ldg(0); sts(0); ldg(1);
    __syncthreads();

    for (int s = 0; s < NS1; s++) {
        const uint32_t* As = (const uint32_t*)(smem + SM_A + (s & 1) * ABYTES);
        const uint32_t* Bs = (const uint32_t*)(smem + SM_B + (s & 1) * BBYTES);
#pragma unroll
        for (int kh = 0; kh < 4; kh++) {
            uint32_t a[4][4];
#pragma unroll
            for (int mt = 0; mt < 4; mt++) {
                int r = wrow + mt * 16 + g;
                a[mt][0] = As[r * ASTR + kh * 8 + t4];
                a[mt][1] = As[(r + 8) * ASTR + kh * 8 + t4];
                a[mt][2] = As[r * ASTR + kh * 8 + t4 + 4];
                a[mt][3] = As[(r + 8) * ASTR + kh * 8 + t4 + 4];
            }
            uint32_t b[4][2];
#pragma unroll
            for (int nt = 0; nt < 4; nt++) {
                b[nt][0] = Bs[(kh * 8 + t4) * BSTR + nb + nt * 8 + g];
                b[nt][1] = Bs[(kh * 8 + t4 + 4) * BSTR + nb + nt * 8 + g];
            }
#pragma unroll
            for (int nt = 0; nt < 4; nt++)
#pragma unroll
                for (int mt = 0; mt < 4; mt++)
                    mma_tf32(acc[mt][nt], a[mt], b[nt][0], b[nt][1]);
        }
        if (s + 1 < NS1) {
            sts(s + 1);
            if (s + 2 < NS1) ldg(s + 2);
        }
        __syncthreads();
    }

    // epilogue: fused SwiGLU (nt pairs (0,1),(2,3) are gate/up of the same logical cols)
#pragma unroll
    for (int mt = 0; mt < 4; mt++) {
        int r = wrow + mt * 16 + g;
#pragma unroll
        for (int pp = 0; pp < 2; pp++) {
            int hc = n0p + (2 * nw + pp) * 8 + 2 * t4;
            const float* ga = acc[mt][2 * pp];
            const float* ua = acc[mt][2 * pp + 1];
            if (r < rows) {
                float2 h;
                h.x = rnaf(silu(ga[0]) * ua[0]);
                h.y = rnaf(silu(ga[1]) * ua[1]);
                *(float2*)(g_hinter + (size_t)(off + r0 + r) * II + hc) = h;
            }
            if (r + 8 < rows) {
                float2 h;
                h.x = rnaf(silu(ga[2]) * ua[2]);
                h.y = rnaf(silu(ga[3]) * ua[3]);
                *(float2*)(g_hinter + (size_t)(off + r0 + r + 8) * II + hc) = h;
            }
        }
    }
}

// ======================= GEMM2: h_inter @ w2 -> scattered out =======================
// grid (MAXT, HH/128)
__global__ __launch_bounds__(256, 2) void gemm2_kernel(const float* __restrict__ w2,
                                                       float* __restrict__ out) {
    extern __shared__ __align__(16) char smem[];
    const int mtile = blockIdx.x;
    if (mtile >= g_nmt) return;
    const int chunk = blockIdx.y;
    const int e = g_mt_e[mtile], r0 = g_mt_r[mtile];
    const int off = g_off[e], ne = g_off[e + 1] - off;
    const int rows = min(BM, ne - r0);

    const int tid = threadIdx.x, wid = tid >> 5, lane = tid & 31;
    const int g = lane >> 2, t4 = lane & 3;
    const int mw = wid & 1, nw = wid >> 1;
    const int wrow = mw * 64, nb = nw * 32;

    const float* wb = w2 + (size_t)e * II * HH;
    const float* abase = g_hinter + (size_t)(off + r0) * II;
    const int n0 = chunk * 128;

    const int f = tid & 7;
    const int rowb = tid >> 3;
    const int c4 = tid & 31;
    const int kkb = tid >> 5;

    const float* aSrc[4];
#pragma unroll
    for (int j = 0; j < 4; j++) {
        int row = rowb + 32 * j;
        aSrc[j] = abase + (size_t)((row < rows) ? row : 0) * II + f * 4;
    }
    const float* bSrc = wb + (size_t)kkb * HH + n0 + c4 * 4;
    const int aOff0 = rowb * ASTR + f * 4;
    const int bOff0 = kkb * BSTR + c4 * 4;

    float4 pa[4], pb[4];
    auto ldg = [&](int s) {
        const int k0 = s * BK;
#pragma unroll
        for (int j = 0; j < 4; j++) {
            pa[j] = *(const float4*)(aSrc[j] + k0);
            pb[j] = *(const float4*)(bSrc + (size_t)k0 * HH + (size_t)j * 8 * HH);
        }
    };
    auto sts = [&](int s) {
        float* A = (float*)(smem + SM_A + (s & 1) * ABYTES);
        float* B = (float*)(smem + SM_B + (s & 1) * BBYTES);
#pragma unroll
        for (int j = 0; j < 4; j++) {
            float4 rb = make_float4(rnaf(pb[j].x), rnaf(pb[j].y), rnaf(pb[j].z), rnaf(pb[j].w));
            *(float4*)(A + aOff0 + j * 32 * ASTR) = pa[j];   // hinter already tf32-rounded
            *(float4*)(B + bOff0 + j * 8 * BSTR) = rb;
        }
    };

    float acc[4][4][4];
#pragma unroll
    for (int a = 0; a < 4; a++)
#pragma unroll
        for (int b = 0; b < 4; b++)
#pragma unroll
            for (int q = 0; q < 4; q++) acc[a][b][q] = 0.0f;

    ldg(0); sts(0); ldg(1);
    __syncthreads();

    for (int s = 0; s < NS2; s++) {
        const uint32_t* As = (const uint32_t*)(smem + SM_A + (s & 1) * ABYTES);
        const uint32_t* Bs = (const uint32_t*)(smem + SM_B + (s & 1) * BBYTES);
#pragma unroll
        for (int kh = 0; kh < 4; kh++) {
            uint32_t a[4][4];
#pragma unroll
            for (int mt = 0; mt < 4; mt++) {
                int r = wrow + mt * 16 + g;
                a[mt][0] = As[r * ASTR + kh * 8 + t4];
                a[mt][1] = As[(r + 8) * ASTR + kh * 8 + t4];
                a[mt][2] = As[r * ASTR + kh * 8 + t4 + 4];
                a[mt][3] = As[(r + 8) * ASTR + kh * 8 + t4 + 4];
            }
            uint32_t b[4][2];
#pragma unroll
            for (int nt = 0; nt < 4; nt++) {
                b[nt][0] = Bs[(kh * 8 + t4) * BSTR + nb + nt * 8 + g];
                b[nt][1] = Bs[(kh * 8 + t4 + 4) * BSTR + nb + nt * 8 + g];
            }
#pragma unroll
            for (int nt = 0; nt < 4; nt++)
#pragma unroll
                for (int mt = 0; mt < 4; mt++)
                    mma_tf32(acc[mt][nt], a[mt], b[nt][0], b[nt][1]);
        }
        if (s + 1 < NS2) {
            sts(s + 1);
            if (s + 2 < NS2) ldg(s + 2);
        }
        __syncthreads();
    }

    // epilogue: scatter rows via perm (layout proven in R3)
#pragma unroll
    for (int mt = 0; mt < 4; mt++) {
        int r = wrow + mt * 16 + g;
        int pair0 = (r < rows) ? g_perm[off + r0 + r] : -1;
        int pair1 = (r + 8 < rows) ? g_perm[off + r0 + r + 8] : -1;
#pragma unroll
        for (int nt = 0; nt < 4; nt++) {
            int col = n0 + nb + nt * 8 + 2 * t4;
            if (pair0 >= 0)
                *(float2*)(out + (size_t)pair0 * HH + col) =
                    make_float2(acc[mt][nt][0], acc[mt][nt][1]);
            if (pair1 >= 0)
                *(float2*)(out + (size_t)pair1 * HH + col) =
                    make_float2(acc[mt][nt][2], acc[mt][nt][3]);
        }
    }
}

// ---------------- launch ----------------
extern "C" void kernel_launch(void* const* d_in, const int* in_sizes, int n_in,
                              void* d_out, int out_size) {
    const float* x    = (const float*)d_in[0];
    const int*   eidx = (const int*)d_in[1];
    const float* w13  = (const float*)d_in[2];
    const float* w2   = (const float*)d_in[3];
    float* out = (float*)d_out;

    cudaFuncSetAttribute(gemm1_kernel, cudaFuncAttributeMaxDynamicSharedMemorySize, SM_TOT);
    cudaFuncSetAttribute(gemm2_kernel, cudaFuncAttributeMaxDynamicSharedMemorySize, SM_TOT);

    route_kernel<<<1, 1024>>>(eidx);
    gemm1_kernel<<<dim3(MAXT, II / 64), 256, SM_TOT>>>(x, w13);
    gemm2_kernel<<<dim3(MAXT, HH / 128), 256, SM_TOT>>>(w2, out);
}